// round 3
// baseline (speedup 1.0000x reference)
#include <cuda_runtime.h>

// 2-layer LSTM (B=256, T=512, I=64, H=256) + FC(H->1), fp32.
// Persistent kernel, f32x2 packed FFMA2 inner product, per-group (16-CTA)
// software barriers. Input projection folded into the per-step GEMM.

#define BB   256
#define TT   512
#define II   64
#define HH   256

#define GRID 128
#define NTHR 128
#define KC   32
#define GSIZE 16          // CTAs per m-group (j-slices)

typedef unsigned long long ull;

// ---------------- device globals (scratch) ---------------------------------
__device__ float g_hbuf[2][BB * HH];
__device__ float g_h1[(size_t)BB * TT * HH];
__device__ ull          g_gen8[8 * 32];    // one counter per group, 256B apart
__device__ unsigned int g_cnt8[8 * 32];

// ---------------- per-group barrier ----------------------------------------
__device__ __forceinline__ void group_barrier(int g) {
    __syncthreads();
    __threadfence();
    if (threadIdx.x == 0) {
        volatile ull* genp = &g_gen8[g * 32];
        ull my = *genp;
        unsigned prev = atomicAdd(&g_cnt8[g * 32], 1u);
        if (prev == GSIZE - 1u) {
            g_cnt8[g * 32] = 0u;
            __threadfence();
            atomicAdd((ull*)&g_gen8[g * 32], 1ULL);
        } else {
            while (*genp == my) __nanosleep(32);
        }
        __threadfence();
    }
    __syncthreads();
}

// ---------------- packed f32x2 helpers -------------------------------------
__device__ __forceinline__ void fma2(ull& d, ull a, ull b) {
    asm("fma.rn.f32x2 %0, %1, %2, %0;" : "+l"(d) : "l"(a), "l"(b));
}
__device__ __forceinline__ float2 unpack2(ull v) {
    float2 f;
    asm("mov.b64 {%0, %1}, %2;" : "=f"(f.x), "=f"(f.y) : "l"(v));
    return f;
}

// ---------------- activations ----------------------------------------------
__device__ __forceinline__ float fsigmoid(float x) {
    return 1.0f / (1.0f + __expf(-x));
}
__device__ __forceinline__ float ftanh(float x) {
    x = fminf(15.0f, fmaxf(-15.0f, x));
    float t = __expf(2.0f * x);
    return (t - 1.0f) / (t + 1.0f);
}

// ---------------- shared memory --------------------------------------------
// Ws2 holds weights pre-duplicated as {w,w} pairs so the inner loop needs no
// packing movs. Row stride 140 floats: 560B (16B-aligned rows) and only a
// mild 4-way conflict on the (rare) staging stores.
struct __align__(16) Smem {
    union {
        float As[2][KC][36];     // h/x tile, k-major, batch-contiguous
        float Sg[32][68];        // gate pre-activations (used after GEMM)
    };
    float Ws2[2][KC][140];       // duplicated weight tile: [k][2*cc] = {w,w}
    float cs[32][16];            // cell state, persistent per layer
    float bias_s[64];
};  // ~47.4 KB

// ---------------- tile loads -----------------------------------------------
template<int KIN>
__device__ __forceinline__ void load_A(float4 (&ar)[2], int cidx, int t, int mbase,
                                       const float* __restrict__ hr,
                                       const float* __restrict__ xin) {
    const bool hpart = (cidx * KC < HH);
#pragma unroll
    for (int i = 0; i < 2; i++) {
        int idx = threadIdx.x + i * NTHR;
        int bb  = idx >> 3;
        int k   = cidx * KC + (idx & 7) * 4;
        const float* src;
        if (hpart) src = hr + (mbase + bb) * HH + k;
        else       src = xin + (mbase + bb) * TT * KIN + t * KIN + (k - HH);
        ar[i] = __ldcg((const float4*)src);
    }
}

__device__ __forceinline__ void store_A(Smem& sm, int buf, const float4 (&ar)[2]) {
#pragma unroll
    for (int i = 0; i < 2; i++) {
        int idx = threadIdx.x + i * NTHR;
        int bb  = idx >> 3;
        int k4  = (idx & 7) * 4;
        sm.As[buf][k4 + 0][bb] = ar[i].x;
        sm.As[buf][k4 + 1][bb] = ar[i].y;
        sm.As[buf][k4 + 2][bb] = ar[i].z;
        sm.As[buf][k4 + 3][bb] = ar[i].w;
    }
}

template<int KIN>
__device__ __forceinline__ void load_W(float4 (&wr)[4], int cidx, int jbase,
                                       const float* __restrict__ Wih,
                                       const float* __restrict__ Whh) {
    const bool hpart = (cidx * KC < HH);
#pragma unroll
    for (int i = 0; i < 4; i++) {
        int idx  = threadIdx.x + i * NTHR;
        int cc   = idx >> 3;
        int k4   = (idx & 7) * 4;
        int gate = cc >> 4, u = cc & 15;
        int grow = gate * HH + jbase + u;
        const float* src;
        if (hpart) src = Whh + grow * HH + cidx * KC + k4;
        else       src = Wih + grow * KIN + cidx * KC + k4 - HH;
        wr[i] = *(const float4*)src;
    }
}

__device__ __forceinline__ void store_Wdup(Smem& sm, int buf, const float4 (&wr)[4]) {
#pragma unroll
    for (int i = 0; i < 4; i++) {
        int idx = threadIdx.x + i * NTHR;
        int cc  = idx >> 3;
        int k4  = (idx & 7) * 4;
        float v[4] = {wr[i].x, wr[i].y, wr[i].z, wr[i].w};
#pragma unroll
        for (int j = 0; j < 4; j++) {
            float2 d = make_float2(v[j], v[j]);
            *(float2*)&sm.Ws2[buf][k4 + j][2 * cc] = d;
        }
    }
}

// ---------------- one LSTM layer -------------------------------------------
template<int KIN, bool ARCHIVE>
__device__ void run_layer(Smem& sm, const float* __restrict__ xin,
                          const float* __restrict__ Wih,
                          const float* __restrict__ Whh,
                          const float* __restrict__ bih,
                          const float* __restrict__ bhh) {
    const int tid   = threadIdx.x;
    const int grp   = blockIdx.x >> 4;
    const int mbase = grp * 32;
    const int jbase = (blockIdx.x & 15) * 16;
    constexpr int NCH = (HH + KIN) / KC;

    for (int idx = tid; idx < 32 * 16; idx += NTHR) {
        int bb = idx >> 4, u = idx & 15;
        sm.cs[bb][u] = 0.0f;
        __stcg(&g_hbuf[0][(mbase + bb) * HH + jbase + u], 0.0f);
    }
    if (tid < 64) {
        int gate = tid >> 4, u = tid & 15;
        int grow = gate * HH + jbase + u;
        sm.bias_s[tid] = bih[grow] + bhh[grow];
    }
    group_barrier(grp);

    const int tb4 = (tid & 7) * 4;
    const int tc8 = (tid >> 3) * 8;    // = 2 * tc4 (duplicated-W index)

    for (int t = 0; t < TT; t++) {
        const float* hr = g_hbuf[t & 1];
        float*       hw = g_hbuf[(t & 1) ^ 1];

        ull acc2[2][4];
#pragma unroll
        for (int p = 0; p < 2; p++)
#pragma unroll
            for (int c = 0; c < 4; c++) acc2[p][c] = 0ULL;

        float4 ar[2], wr[4];
        load_A<KIN>(ar, 0, t, mbase, hr, xin);
        load_W<KIN>(wr, 0, jbase, Wih, Whh);
        store_A(sm, 0, ar);
        store_Wdup(sm, 0, wr);
        __syncthreads();

        for (int c = 0; c < NCH; c++) {
            const bool more = (c + 1 < NCH);
            if (more) {
                load_A<KIN>(ar, c + 1, t, mbase, hr, xin);
                load_W<KIN>(wr, c + 1, jbase, Wih, Whh);
            }
            const int buf = c & 1;
#pragma unroll 8
            for (int kk = 0; kk < KC; kk++) {
                ulonglong2 av  = *(const ulonglong2*)&sm.As[buf][kk][tb4];
                ulonglong2 w01 = *(const ulonglong2*)&sm.Ws2[buf][kk][tc8];
                ulonglong2 w23 = *(const ulonglong2*)&sm.Ws2[buf][kk][tc8 + 4];
                fma2(acc2[0][0], av.x, w01.x); fma2(acc2[0][1], av.x, w01.y);
                fma2(acc2[0][2], av.x, w23.x); fma2(acc2[0][3], av.x, w23.y);
                fma2(acc2[1][0], av.y, w01.x); fma2(acc2[1][1], av.y, w01.y);
                fma2(acc2[1][2], av.y, w23.x); fma2(acc2[1][3], av.y, w23.y);
            }
            if (more) {
                store_A(sm, buf ^ 1, ar);
                store_Wdup(sm, buf ^ 1, wr);
            }
            __syncthreads();
        }

        // Unpack f32x2 accumulators -> Sg (overlays As; all As reads are done)
        const int tb = tid & 7, tc = tid >> 3;
        float vrow[4][4];
#pragma unroll
        for (int p = 0; p < 2; p++)
#pragma unroll
            for (int c = 0; c < 4; c++) {
                float2 f = unpack2(acc2[p][c]);
                vrow[2 * p + 0][c] = f.x;
                vrow[2 * p + 1][c] = f.y;
            }
#pragma unroll
        for (int rr = 0; rr < 4; rr++)
            *(float4*)&sm.Sg[tb * 4 + rr][tc * 4] =
                make_float4(vrow[rr][0], vrow[rr][1], vrow[rr][2], vrow[rr][3]);
        __syncthreads();

#pragma unroll
        for (int r = 0; r < 4; r++) {
            int pair = tid * 4 + r;
            int bb = pair >> 4;
            int u  = pair & 15;
            float pi = sm.Sg[bb][u]      + sm.bias_s[u];
            float pf = sm.Sg[bb][16 + u] + sm.bias_s[16 + u];
            float pg = sm.Sg[bb][32 + u] + sm.bias_s[32 + u];
            float po = sm.Sg[bb][48 + u] + sm.bias_s[48 + u];
            float ig = fsigmoid(pi);
            float fg = fsigmoid(pf);
            float gg = ftanh(pg);
            float og = fsigmoid(po);
            float cv = fg * sm.cs[bb][u] + ig * gg;
            sm.cs[bb][u] = cv;
            float hv = og * ftanh(cv);
            __stcg(&hw[(mbase + bb) * HH + jbase + u], hv);
            if (ARCHIVE)
                __stcg(&g_h1[(size_t)((mbase + bb) * TT + t) * HH + jbase + u], hv);
        }
        group_barrier(grp);
    }
}

// ---------------- full model -----------------------------------------------
__global__ void __launch_bounds__(NTHR, 1)
lstm_persistent_kernel(const float* __restrict__ x,
                       const float* __restrict__ Wih0, const float* __restrict__ Whh0,
                       const float* __restrict__ bih0, const float* __restrict__ bhh0,
                       const float* __restrict__ Wih1, const float* __restrict__ Whh1,
                       const float* __restrict__ bih1, const float* __restrict__ bhh1,
                       const float* __restrict__ Wfc,  const float* __restrict__ bfc,
                       float* __restrict__ out) {
    __shared__ Smem sm;

    run_layer<II, true >(sm, x,    Wih0, Whh0, bih0, bhh0);
    run_layer<HH, false>(sm, g_h1, Wih1, Whh1, bih1, bhh1);
    // final h2 sits in g_hbuf[0]; last group barrier already passed

    if ((blockIdx.x & 15) == 0) {
        int mbase = (blockIdx.x >> 4) * 32;
        for (int bb = threadIdx.x; bb < 32; bb += NTHR) {
            float s = bfc[0];
#pragma unroll 8
            for (int j = 0; j < HH; j++)
                s += __ldcg(&g_hbuf[0][(mbase + bb) * HH + j]) * Wfc[j];
            out[mbase + bb] = s;
        }
    }
}

// ---------------- harness entry --------------------------------------------
extern "C" void kernel_launch(void* const* d_in, const int* in_sizes, int n_in,
                              void* d_out, int out_size) {
    (void)in_sizes; (void)n_in; (void)out_size;
    const float* x    = (const float*)d_in[0];
    const float* Wih0 = (const float*)d_in[1];
    const float* Whh0 = (const float*)d_in[2];
    const float* bih0 = (const float*)d_in[3];
    const float* bhh0 = (const float*)d_in[4];
    const float* Wih1 = (const float*)d_in[5];
    const float* Whh1 = (const float*)d_in[6];
    const float* bih1 = (const float*)d_in[7];
    const float* bhh1 = (const float*)d_in[8];
    const float* Wfc  = (const float*)d_in[9];
    const float* bfc  = (const float*)d_in[10];

    lstm_persistent_kernel<<<GRID, NTHR>>>(x, Wih0, Whh0, bih0, bhh0,
                                           Wih1, Whh1, bih1, bhh1,
                                           Wfc, bfc, (float*)d_out);
}

// round 6
// speedup vs baseline: 1.4031x; 1.4031x over previous
#include <cuda_runtime.h>

// 2-layer LSTM (B=256, T=512, I=64, H=256) + FC(H->1), fp32.
// Persistent kernel, 128 CTAs x 256 threads. CTA tile: 32 batch x 16 units.
// Weights resident in dynamic shared memory for the whole layer (written once).
// A (=[h | x]) staged k-major into smem each step; non-recurrent part
// prefetched before the group barrier. 16-CTA group barriers.

#define BB   256
#define TT   512
#define II   64
#define HH   256

#define GRID 128
#define NTHR 256
#define GSIZE 16

typedef unsigned long long ull;

// ---------------- device globals (scratch) ---------------------------------
__device__ float g_hbuf[2][BB * HH];
__device__ float g_h1[(size_t)BB * TT * HH];
__device__ ull          g_gen8[8 * 32];
__device__ unsigned int g_cnt8[8 * 32];

// ---------------- per-group (16 CTA) barrier --------------------------------
__device__ __forceinline__ void group_barrier(int g) {
    __syncthreads();
    __threadfence();
    if (threadIdx.x == 0) {
        volatile ull* genp = &g_gen8[g * 32];
        ull my = *genp;
        unsigned prev = atomicAdd(&g_cnt8[g * 32], 1u);
        if (prev == GSIZE - 1u) {
            g_cnt8[g * 32] = 0u;
            __threadfence();
            atomicAdd((ull*)&g_gen8[g * 32], 1ULL);
        } else {
            while (*genp == my) __nanosleep(32);
        }
        __threadfence();
    }
    __syncthreads();
}

// ---------------- activations ----------------------------------------------
__device__ __forceinline__ float fsigmoid(float x) {
    return 1.0f / (1.0f + __expf(-x));
}
__device__ __forceinline__ float ftanh(float x) {
    x = fminf(15.0f, fmaxf(-15.0f, x));
    float t = __expf(2.0f * x);
    return (t - 1.0f) / (t + 1.0f);
}

// Dynamic smem layout (floats), K = HH + KIN:
//   ws   [K][66]   weight slice, k-major, cols = 64 gate-cols (stride 66)
//   as   [K][36]   A tile, k-major, batch-contiguous (stride 36)
//   sg   [32][68]  gate pre-activations (overlays 'as' rows 0..60)
//   cs   [512]     cell state tile [b][u]
//   bias [64]
extern __shared__ float smbuf[];

// ---------------- A staging: chunk = 32 k-rows ------------------------------
template<int KIN>
__device__ __forceinline__ void stage_A(float* as, int c0, int c1, int t, int mbase,
                                        const float* __restrict__ hr,
                                        const float* __restrict__ xin) {
    const int tid = threadIdx.x;
    const int bb  = tid >> 3;
    const int kof = (tid & 7) * 4;
    for (int c = c0; c < c1; c++) {
        int k = c * 32 + kof;
        const float* src;
        if (k < HH) src = hr + (mbase + bb) * HH + k;
        else {
            if (KIN == HH)      // layer 1: xin = g_h1 [b][t][HH]
                src = xin + ((size_t)(mbase + bb) * TT + t) * HH + (k - HH);
            else                // layer 0: xin = x [b][t][II]
                src = xin + ((size_t)(mbase + bb) * TT + t) * II + (k - HH);
        }
        float4 a = __ldcg((const float4*)src);
        as[(k + 0) * 36 + bb] = a.x;
        as[(k + 1) * 36 + bb] = a.y;
        as[(k + 2) * 36 + bb] = a.z;
        as[(k + 3) * 36 + bb] = a.w;
    }
}

// ---------------- one LSTM layer -------------------------------------------
template<int KIN, bool ARCHIVE>
__device__ void run_layer(const float* __restrict__ xin,
                          const float* __restrict__ Wih,
                          const float* __restrict__ Whh,
                          const float* __restrict__ bih,
                          const float* __restrict__ bhh) {
    constexpr int K = HH + KIN;
    float* ws   = smbuf;                 // [K][66]
    float* as   = smbuf + K * 66;        // [K][36]
    float* sg   = as;                    // overlay [32][68]
    float* cs   = as + K * 36;           // [512]
    float* bias = cs + 512;              // [64]

    const int tid   = threadIdx.x;
    const int grp   = blockIdx.x >> 4;
    const int mbase = grp * 32;
    const int jbase = (blockIdx.x & 15) * 16;

    // ---- init: weight slice -> smem (once), zero c, zero h(-1), biases ----
    constexpr int K4 = K / 4;            // 80 or 128
#pragma unroll 4
    for (int i = 0; i < K / 16; i++) {   // K*16 float4s / 256 threads
        int idx = tid + i * NTHR;
        int cc  = idx / K4;
        int k   = (idx - cc * K4) * 4;
        int gate = cc >> 4, u = cc & 15;
        int grow = gate * HH + jbase + u;
        const float* src = (k < HH) ? (Whh + grow * HH + k)
                                    : (Wih + grow * KIN + k - HH);
        float4 w = *(const float4*)src;
        ws[(k + 0) * 66 + cc] = w.x;
        ws[(k + 1) * 66 + cc] = w.y;
        ws[(k + 2) * 66 + cc] = w.z;
        ws[(k + 3) * 66 + cc] = w.w;
    }
    if (tid < 512) cs[tid] = 0.0f;
    if (tid < 512) {
        int bb = tid >> 4, u = tid & 15;
        __stcg(&g_hbuf[0][(mbase + bb) * HH + jbase + u], 0.0f);
    }
    if (tid < 64) {
        int gate = tid >> 4, u = tid & 15;
        int grow = gate * HH + jbase + u;
        bias[tid] = bih[grow] + bhh[grow];
    }
    group_barrier(grp);

    // prologue: stage non-recurrent part for t=0
    stage_A<KIN>(as, HH / 32, K / 32, 0, mbase, nullptr, xin);

    const int b4 = (tid & 7) * 4;
    const int c2 = (tid >> 3) * 2;

    for (int t = 0; t < TT; t++) {
        const float* hr = g_hbuf[t & 1];
        float*       hw = g_hbuf[(t & 1) ^ 1];

        // stage recurrent part (h(t-1))
        stage_A<KIN>(as, 0, HH / 32, t, mbase, hr, xin);
        __syncthreads();

        // ---- GEMM: acc[4b][2c] over full K, W resident ----
        float acc00 = 0.f, acc01 = 0.f, acc10 = 0.f, acc11 = 0.f;
        float acc20 = 0.f, acc21 = 0.f, acc30 = 0.f, acc31 = 0.f;
#pragma unroll 8
        for (int kk = 0; kk < K; kk++) {
            float4 a = *(const float4*)&as[kk * 36 + b4];
            float2 w = *(const float2*)&ws[kk * 66 + c2];
            acc00 += a.x * w.x; acc01 += a.x * w.y;
            acc10 += a.y * w.x; acc11 += a.y * w.y;
            acc20 += a.z * w.x; acc21 += a.z * w.y;
            acc30 += a.w * w.x; acc31 += a.w * w.y;
        }
        __syncthreads();                 // all As reads done before sg overlay

        // ---- stage gate pre-activations ----
        {
            int rb = (tid & 7) * 4;
            *(float2*)&sg[(rb + 0) * 68 + c2] = make_float2(acc00, acc01);
            *(float2*)&sg[(rb + 1) * 68 + c2] = make_float2(acc10, acc11);
            *(float2*)&sg[(rb + 2) * 68 + c2] = make_float2(acc20, acc21);
            *(float2*)&sg[(rb + 3) * 68 + c2] = make_float2(acc30, acc31);
        }
        __syncthreads();

        // ---- LSTM pointwise update: 512 (b,u) pairs / 256 threads ----
#pragma unroll
        for (int r = 0; r < 2; r++) {
            int pair = tid * 2 + r;
            int bb = pair >> 4;
            int u  = pair & 15;
            float pi = sg[bb * 68 + u]      + bias[u];
            float pf = sg[bb * 68 + 16 + u] + bias[16 + u];
            float pg = sg[bb * 68 + 32 + u] + bias[32 + u];
            float po = sg[bb * 68 + 48 + u] + bias[48 + u];
            float ig = fsigmoid(pi);
            float fg = fsigmoid(pf);
            float gg = ftanh(pg);
            float og = fsigmoid(po);
            float cv = fg * cs[bb * 16 + u] + ig * gg;
            cs[bb * 16 + u] = cv;
            float hv = og * ftanh(cv);
            __stcg(&hw[(mbase + bb) * HH + jbase + u], hv);
            if (ARCHIVE)
                __stcg(&g_h1[(size_t)((mbase + bb) * TT + t) * HH + jbase + u], hv);
        }

        // prefetch non-recurrent part for t+1 (disjoint from sg rows; no sync)
        if (t + 1 < TT)
            stage_A<KIN>(as, HH / 32, K / 32, t + 1, mbase, nullptr, xin);

        group_barrier(grp);              // h(t) visible group-wide
    }
}

// ---------------- full model -----------------------------------------------
__global__ void __launch_bounds__(NTHR, 1)
lstm_persistent_kernel(const float* __restrict__ x,
                       const float* __restrict__ Wih0, const float* __restrict__ Whh0,
                       const float* __restrict__ bih0, const float* __restrict__ bhh0,
                       const float* __restrict__ Wih1, const float* __restrict__ Whh1,
                       const float* __restrict__ bih1, const float* __restrict__ bhh1,
                       const float* __restrict__ Wfc,  const float* __restrict__ bfc,
                       float* __restrict__ out) {
    run_layer<II, true >(x,    Wih0, Whh0, bih0, bhh0);
    run_layer<HH, false>(g_h1, Wih1, Whh1, bih1, bhh1);
    // final h2 sits in g_hbuf[0]; last group barrier already passed

    if ((blockIdx.x & 15) == 0) {
        int mbase = (blockIdx.x >> 4) * 32;
        for (int bb = threadIdx.x; bb < 32; bb += NTHR) {
            float s = bfc[0];
#pragma unroll 8
            for (int j = 0; j < HH; j++)
                s += __ldcg(&g_hbuf[0][mbase * HH + bb * HH + j]) * Wfc[j];
            out[mbase + bb] = s;
        }
    }
}

// ---------------- harness entry --------------------------------------------
extern "C" void kernel_launch(void* const* d_in, const int* in_sizes, int n_in,
                              void* d_out, int out_size) {
    (void)in_sizes; (void)n_in; (void)out_size;
    const float* x    = (const float*)d_in[0];
    const float* Wih0 = (const float*)d_in[1];
    const float* Whh0 = (const float*)d_in[2];
    const float* bih0 = (const float*)d_in[3];
    const float* bhh0 = (const float*)d_in[4];
    const float* Wih1 = (const float*)d_in[5];
    const float* Whh1 = (const float*)d_in[6];
    const float* bih1 = (const float*)d_in[7];
    const float* bhh1 = (const float*)d_in[8];
    const float* Wfc  = (const float*)d_in[9];
    const float* bfc  = (const float*)d_in[10];

    // Layer-1 footprint: (512*66 + 512*36 + 512 + 64) floats = 52800 * 4 B
    const int smem_bytes = (512 * 66 + 512 * 36 + 512 + 64) * 4;
    cudaFuncSetAttribute(lstm_persistent_kernel,
                         cudaFuncAttributeMaxDynamicSharedMemorySize, smem_bytes);

    lstm_persistent_kernel<<<GRID, NTHR, smem_bytes>>>(
        x, Wih0, Whh0, bih0, bhh0,
        Wih1, Whh1, bih1, bhh1,
        Wfc, bfc, (float*)d_out);
}

// round 7
// speedup vs baseline: 1.4041x; 1.0007x over previous
#include <cuda_runtime.h>

// 2-layer LSTM (B=256, T=512, I=64, H=256) + FC(H->1), fp32.
// Persistent kernel, 128 CTAs x 256 threads. CTA tile: 32 batch x 16 units.
// Weights resident in dynamic shared memory for the whole layer.
// Inner product via packed fma.rn.f32x2 (FFMA2): batch-pairs from the
// batch-contiguous A tile, W duplicated into both halves via register movs.

#define BB   256
#define TT   512
#define II   64
#define HH   256

#define GRID 128
#define NTHR 256
#define GSIZE 16

typedef unsigned long long ull;

// ---------------- device globals (scratch) ---------------------------------
__device__ float g_hbuf[2][BB * HH];
__device__ float g_h1[(size_t)BB * TT * HH];
__device__ ull          g_gen8[8 * 32];
__device__ unsigned int g_cnt8[8 * 32];

// ---------------- per-group (16 CTA) barrier --------------------------------
__device__ __forceinline__ void group_barrier(int g) {
    __syncthreads();
    __threadfence();
    if (threadIdx.x == 0) {
        volatile ull* genp = &g_gen8[g * 32];
        ull my = *genp;
        unsigned prev = atomicAdd(&g_cnt8[g * 32], 1u);
        if (prev == GSIZE - 1u) {
            g_cnt8[g * 32] = 0u;
            __threadfence();
            atomicAdd((ull*)&g_gen8[g * 32], 1ULL);
        } else {
            while (*genp == my) __nanosleep(32);
        }
        __threadfence();
    }
    __syncthreads();
}

// ---------------- packed f32x2 helpers -------------------------------------
__device__ __forceinline__ void fma2(ull& d, ull a, ull b) {
    asm("fma.rn.f32x2 %0, %1, %2, %0;" : "+l"(d) : "l"(a), "l"(b));
}
__device__ __forceinline__ ull pack2(float lo, float hi) {
    ull v;
    asm("mov.b64 %0, {%1, %2};" : "=l"(v) : "f"(lo), "f"(hi));
    return v;
}
__device__ __forceinline__ float2 unpack2(ull v) {
    float2 f;
    asm("mov.b64 {%0, %1}, %2;" : "=f"(f.x), "=f"(f.y) : "l"(v));
    return f;
}

// ---------------- activations ----------------------------------------------
__device__ __forceinline__ float fsigmoid(float x) {
    return 1.0f / (1.0f + __expf(-x));
}
__device__ __forceinline__ float ftanh(float x) {
    x = fminf(15.0f, fmaxf(-15.0f, x));
    float t = __expf(2.0f * x);
    return (t - 1.0f) / (t + 1.0f);
}

// Dynamic smem layout (floats), K = HH + KIN:
//   ws   [K][66]   weight slice, k-major, 64 gate-cols (stride 66)
//   as   [K][36]   A tile, k-major, batch-contiguous (stride 36)
//   sg   [32][68]  gate pre-activations (overlays 'as')
//   cs   [512]     cell state tile [b][u]
//   bias [64]
extern __shared__ float smbuf[];

// ---------------- A staging: chunk = 32 k-rows ------------------------------
template<int KIN>
__device__ __forceinline__ void stage_A(float* as, int c0, int c1, int t, int mbase,
                                        const float* __restrict__ hr,
                                        const float* __restrict__ xin) {
    const int tid = threadIdx.x;
    const int bb  = tid >> 3;
    const int kof = (tid & 7) * 4;
    for (int c = c0; c < c1; c++) {
        int k = c * 32 + kof;
        const float* src;
        if (k < HH) src = hr + (mbase + bb) * HH + k;
        else {
            if (KIN == HH)
                src = xin + ((size_t)(mbase + bb) * TT + t) * HH + (k - HH);
            else
                src = xin + ((size_t)(mbase + bb) * TT + t) * II + (k - HH);
        }
        float4 a = __ldcg((const float4*)src);
        as[(k + 0) * 36 + bb] = a.x;
        as[(k + 1) * 36 + bb] = a.y;
        as[(k + 2) * 36 + bb] = a.z;
        as[(k + 3) * 36 + bb] = a.w;
    }
}

// ---------------- one LSTM layer -------------------------------------------
template<int KIN, bool ARCHIVE>
__device__ void run_layer(const float* __restrict__ xin,
                          const float* __restrict__ Wih,
                          const float* __restrict__ Whh,
                          const float* __restrict__ bih,
                          const float* __restrict__ bhh) {
    constexpr int K = HH + KIN;
    float* ws   = smbuf;                 // [K][66]
    float* as   = smbuf + K * 66;        // [K][36]
    float* sg   = as;                    // overlay [32][68]
    float* cs   = as + K * 36;           // [512]
    float* bias = cs + 512;              // [64]

    const int tid   = threadIdx.x;
    const int grp   = blockIdx.x >> 4;
    const int mbase = grp * 32;
    const int jbase = (blockIdx.x & 15) * 16;

    // ---- init: weight slice -> smem (once), zero c, zero h(-1), biases ----
    constexpr int K4 = K / 4;
#pragma unroll 4
    for (int i = 0; i < K / 16; i++) {
        int idx = tid + i * NTHR;
        int cc  = idx / K4;
        int k   = (idx - cc * K4) * 4;
        int gate = cc >> 4, u = cc & 15;
        int grow = gate * HH + jbase + u;
        const float* src = (k < HH) ? (Whh + grow * HH + k)
                                    : (Wih + grow * KIN + k - HH);
        float4 w = *(const float4*)src;
        ws[(k + 0) * 66 + cc] = w.x;
        ws[(k + 1) * 66 + cc] = w.y;
        ws[(k + 2) * 66 + cc] = w.z;
        ws[(k + 3) * 66 + cc] = w.w;
    }
    if (tid < 512) cs[tid] = 0.0f;
    if (tid < 512) {
        int bb = tid >> 4, u = tid & 15;
        __stcg(&g_hbuf[0][(mbase + bb) * HH + jbase + u], 0.0f);
    }
    if (tid < 64) {
        int gate = tid >> 4, u = tid & 15;
        int grow = gate * HH + jbase + u;
        bias[tid] = bih[grow] + bhh[grow];
    }
    group_barrier(grp);

    stage_A<KIN>(as, HH / 32, K / 32, 0, mbase, nullptr, xin);

    const int b4 = (tid & 7) * 4;
    const int c2 = (tid >> 3) * 2;

    for (int t = 0; t < TT; t++) {
        const float* hr = g_hbuf[t & 1];
        float*       hw = g_hbuf[(t & 1) ^ 1];

        stage_A<KIN>(as, 0, HH / 32, t, mbase, hr, xin);
        __syncthreads();

        // ---- GEMM: 4 batch x 2 cols per thread, packed f32x2 ----
        // acc2[0]={b0c0,b1c0}  acc2[1]={b0c1,b1c1}
        // acc2[2]={b2c0,b3c0}  acc2[3]={b2c1,b3c1}
        ull acc2[4] = {0ULL, 0ULL, 0ULL, 0ULL};
#pragma unroll 8
        for (int kk = 0; kk < K; kk++) {
            ulonglong2 av = *(const ulonglong2*)&as[kk * 36 + b4];  // {b0,b1},{b2,b3}
            float2 w = *(const float2*)&ws[kk * 66 + c2];
            ull wxx = pack2(w.x, w.x);
            ull wyy = pack2(w.y, w.y);
            fma2(acc2[0], av.x, wxx);
            fma2(acc2[1], av.x, wyy);
            fma2(acc2[2], av.y, wxx);
            fma2(acc2[3], av.y, wyy);
        }
        __syncthreads();                 // all As reads done before sg overlay

        // ---- stage gate pre-activations ----
        {
            float2 f0 = unpack2(acc2[0]);   // {b0c0, b1c0}
            float2 f1 = unpack2(acc2[1]);   // {b0c1, b1c1}
            float2 f2 = unpack2(acc2[2]);   // {b2c0, b3c0}
            float2 f3 = unpack2(acc2[3]);   // {b2c1, b3c1}
            int rb = (tid & 7) * 4;
            *(float2*)&sg[(rb + 0) * 68 + c2] = make_float2(f0.x, f1.x);
            *(float2*)&sg[(rb + 1) * 68 + c2] = make_float2(f0.y, f1.y);
            *(float2*)&sg[(rb + 2) * 68 + c2] = make_float2(f2.x, f3.x);
            *(float2*)&sg[(rb + 3) * 68 + c2] = make_float2(f2.y, f3.y);
        }
        __syncthreads();

        // ---- LSTM pointwise update: 512 (b,u) pairs / 256 threads ----
#pragma unroll
        for (int r = 0; r < 2; r++) {
            int pair = tid * 2 + r;
            int bb = pair >> 4;
            int u  = pair & 15;
            float pi = sg[bb * 68 + u]      + bias[u];
            float pf = sg[bb * 68 + 16 + u] + bias[16 + u];
            float pg = sg[bb * 68 + 32 + u] + bias[32 + u];
            float po = sg[bb * 68 + 48 + u] + bias[48 + u];
            float ig = fsigmoid(pi);
            float fg = fsigmoid(pf);
            float gg = ftanh(pg);
            float og = fsigmoid(po);
            float cv = fg * cs[bb * 16 + u] + ig * gg;
            cs[bb * 16 + u] = cv;
            float hv = og * ftanh(cv);
            __stcg(&hw[(mbase + bb) * HH + jbase + u], hv);
            if (ARCHIVE)
                __stcg(&g_h1[(size_t)((mbase + bb) * TT + t) * HH + jbase + u], hv);
        }

        if (t + 1 < TT)
            stage_A<KIN>(as, HH / 32, K / 32, t + 1, mbase, nullptr, xin);

        group_barrier(grp);
    }
}

// ---------------- full model -----------------------------------------------
__global__ void __launch_bounds__(NTHR, 1)
lstm_persistent_kernel(const float* __restrict__ x,
                       const float* __restrict__ Wih0, const float* __restrict__ Whh0,
                       const float* __restrict__ bih0, const float* __restrict__ bhh0,
                       const float* __restrict__ Wih1, const float* __restrict__ Whh1,
                       const float* __restrict__ bih1, const float* __restrict__ bhh1,
                       const float* __restrict__ Wfc,  const float* __restrict__ bfc,
                       float* __restrict__ out) {
    run_layer<II, true >(x,    Wih0, Whh0, bih0, bhh0);
    run_layer<HH, false>(g_h1, Wih1, Whh1, bih1, bhh1);

    if ((blockIdx.x & 15) == 0) {
        int mbase = (blockIdx.x >> 4) * 32;
        for (int bb = threadIdx.x; bb < 32; bb += NTHR) {
            float s = bfc[0];
#pragma unroll 8
            for (int j = 0; j < HH; j++)
                s += __ldcg(&g_hbuf[0][(mbase + bb) * HH + j]) * Wfc[j];
            out[mbase + bb] = s;
        }
    }
}

// ---------------- harness entry --------------------------------------------
extern "C" void kernel_launch(void* const* d_in, const int* in_sizes, int n_in,
                              void* d_out, int out_size) {
    (void)in_sizes; (void)n_in; (void)out_size;
    const float* x    = (const float*)d_in[0];
    const float* Wih0 = (const float*)d_in[1];
    const float* Whh0 = (const float*)d_in[2];
    const float* bih0 = (const float*)d_in[3];
    const float* bhh0 = (const float*)d_in[4];
    const float* Wih1 = (const float*)d_in[5];
    const float* Whh1 = (const float*)d_in[6];
    const float* bih1 = (const float*)d_in[7];
    const float* bhh1 = (const float*)d_in[8];
    const float* Wfc  = (const float*)d_in[9];
    const float* bfc  = (const float*)d_in[10];

    const int smem_bytes = (512 * 66 + 512 * 36 + 512 + 64) * 4;
    cudaFuncSetAttribute(lstm_persistent_kernel,
                         cudaFuncAttributeMaxDynamicSharedMemorySize, smem_bytes);

    lstm_persistent_kernel<<<GRID, NTHR, smem_bytes>>>(
        x, Wih0, Whh0, bih0, bhh0,
        Wih1, Whh1, bih1, bhh1,
        Wfc, bfc, (float*)d_out);
}

// round 9
// speedup vs baseline: 1.6013x; 1.1404x over previous
#include <cuda_runtime.h>

// 2-layer LSTM (B=256, T=512, I=64, H=256) + FC(H->1), fp32.
// Persistent kernel, 128 CTAs x 128 threads. CTA tile: 32 batch x 16 units.
// Weights resident in smem for the whole layer. Per-thread GEMM tile 4b x 4c
// (16 accums) -> 0.5 crossbar phases per MAC (was 0.75). FFMA2 inner product.

#define BB   256
#define TT   512
#define II   64
#define HH   256

#define GRID 128
#define NTHR 128
#define GSIZE 16

typedef unsigned long long ull;

// ---------------- device globals (scratch) ---------------------------------
__device__ float g_hbuf[2][BB * HH];
__device__ float g_h1[(size_t)BB * TT * HH];
__device__ ull          g_gen8[8 * 32];
__device__ unsigned int g_cnt8[8 * 32];

// ---------------- per-group (16 CTA) barrier --------------------------------
__device__ __forceinline__ void group_barrier(int g) {
    __syncthreads();
    __threadfence();
    if (threadIdx.x == 0) {
        volatile ull* genp = &g_gen8[g * 32];
        ull my = *genp;
        unsigned prev = atomicAdd(&g_cnt8[g * 32], 1u);
        if (prev == GSIZE - 1u) {
            g_cnt8[g * 32] = 0u;
            __threadfence();
            atomicAdd((ull*)&g_gen8[g * 32], 1ULL);
        } else {
            while (*genp == my) __nanosleep(32);
        }
        __threadfence();
    }
    __syncthreads();
}

// ---------------- packed f32x2 helpers -------------------------------------
__device__ __forceinline__ void fma2(ull& d, ull a, ull b) {
    asm("fma.rn.f32x2 %0, %1, %2, %0;" : "+l"(d) : "l"(a), "l"(b));
}
__device__ __forceinline__ ull pack2(float lo, float hi) {
    ull v;
    asm("mov.b64 %0, {%1, %2};" : "=l"(v) : "f"(lo), "f"(hi));
    return v;
}
__device__ __forceinline__ float2 unpack2(ull v) {
    float2 f;
    asm("mov.b64 {%0, %1}, %2;" : "=f"(f.x), "=f"(f.y) : "l"(v));
    return f;
}

// ---------------- activations ----------------------------------------------
__device__ __forceinline__ float fsigmoid(float x) {
    return 1.0f / (1.0f + __expf(-x));
}
__device__ __forceinline__ float ftanh(float x) {
    x = fminf(15.0f, fmaxf(-15.0f, x));
    float t = __expf(2.0f * x);
    return (t - 1.0f) / (t + 1.0f);
}

// Dynamic smem layout (floats), K = HH + KIN:
//   ws   [K][68]   weight slice, k-major, 64 gate-cols (stride 68: 272B rows)
//   as   [K][36]   A tile, k-major, batch-contiguous (stride 36)
//   sg   [32][68]  gate pre-activations (overlays 'as' low rows)
//   cs   [512]     cell state tile
//   bias [64]
extern __shared__ float smbuf[];

// ---------------- A staging: chunks of 32 k-rows ----------------------------
template<int KIN>
__device__ __forceinline__ void stage_A(float* as, int c0, int c1, int t, int mbase,
                                        const float* __restrict__ hr,
                                        const float* __restrict__ xin) {
    const int tid = threadIdx.x;
    for (int c = c0; c < c1; c++) {
#pragma unroll
        for (int i = 0; i < 2; i++) {
            int idx = tid + i * NTHR;
            int bb  = idx >> 3;
            int k   = c * 32 + (idx & 7) * 4;
            const float* src;
            if (k < HH) src = hr + (mbase + bb) * HH + k;
            else {
                if (KIN == HH)
                    src = xin + ((size_t)(mbase + bb) * TT + t) * HH + (k - HH);
                else
                    src = xin + ((size_t)(mbase + bb) * TT + t) * II + (k - HH);
            }
            float4 a = __ldcg((const float4*)src);
            as[(k + 0) * 36 + bb] = a.x;
            as[(k + 1) * 36 + bb] = a.y;
            as[(k + 2) * 36 + bb] = a.z;
            as[(k + 3) * 36 + bb] = a.w;
        }
    }
}

// ---------------- one LSTM layer -------------------------------------------
template<int KIN, bool ARCHIVE>
__device__ void run_layer(const float* __restrict__ xin,
                          const float* __restrict__ Wih,
                          const float* __restrict__ Whh,
                          const float* __restrict__ bih,
                          const float* __restrict__ bhh) {
    constexpr int K = HH + KIN;
    float* ws   = smbuf;                 // [K][68]
    float* as   = smbuf + K * 68;        // [K][36]
    float* sg   = as;                    // overlay [32][68]
    float* cs   = as + K * 36;           // [512]
    float* bias = cs + 512;              // [64]

    const int tid   = threadIdx.x;
    const int grp   = blockIdx.x >> 4;
    const int mbase = grp * 32;
    const int jbase = (blockIdx.x & 15) * 16;

    // ---- init: weight slice -> smem (once), zero c / h(-1), biases ----
    constexpr int K4 = K / 4;            // float4s per gate-col
    for (int idx = tid; idx < 64 * K4; idx += NTHR) {
        int cc = idx / K4;
        int k  = (idx - cc * K4) * 4;
        int gate = cc >> 4, u = cc & 15;
        int grow = gate * HH + jbase + u;
        const float* src = (k < HH) ? (Whh + grow * HH + k)
                                    : (Wih + grow * KIN + k - HH);
        float4 w = *(const float4*)src;
        ws[(k + 0) * 68 + cc] = w.x;
        ws[(k + 1) * 68 + cc] = w.y;
        ws[(k + 2) * 68 + cc] = w.z;
        ws[(k + 3) * 68 + cc] = w.w;
    }
    for (int idx = tid; idx < 512; idx += NTHR) {
        cs[idx] = 0.0f;
        int bb = idx >> 4, u = idx & 15;
        __stcg(&g_hbuf[0][(mbase + bb) * HH + jbase + u], 0.0f);
    }
    if (tid < 64) {
        int gate = tid >> 4, u = tid & 15;
        int grow = gate * HH + jbase + u;
        bias[tid] = bih[grow] + bhh[grow];
    }
    group_barrier(grp);

    stage_A<KIN>(as, HH / 32, K / 32, 0, mbase, nullptr, xin);

    const int b4 = (tid & 7) * 4;        // batch offset (0..28)
    const int c4 = (tid >> 3) * 4;       // col offset   (0..60)

    for (int t = 0; t < TT; t++) {
        const float* hr = g_hbuf[t & 1];
        float*       hw = g_hbuf[(t & 1) ^ 1];

        stage_A<KIN>(as, 0, HH / 32, t, mbase, hr, xin);
        __syncthreads();

        // ---- GEMM: 4 batch x 4 cols per thread, packed f32x2 ----
        // acc[p][c] = {b(2p), b(2p+1)} for col c4+c
        ull acc[2][4];
#pragma unroll
        for (int p = 0; p < 2; p++)
#pragma unroll
            for (int c = 0; c < 4; c++) acc[p][c] = 0ULL;

#pragma unroll 8
        for (int kk = 0; kk < K; kk++) {
            ulonglong2 av = *(const ulonglong2*)&as[kk * 36 + b4]; // {b0,b1},{b2,b3}
            float4 w = *(const float4*)&ws[kk * 68 + c4];          // broadcast read
            ull wxx = pack2(w.x, w.x);
            ull wyy = pack2(w.y, w.y);
            ull wzz = pack2(w.z, w.z);
            ull www = pack2(w.w, w.w);
            fma2(acc[0][0], av.x, wxx); fma2(acc[0][1], av.x, wyy);
            fma2(acc[0][2], av.x, wzz); fma2(acc[0][3], av.x, www);
            fma2(acc[1][0], av.y, wxx); fma2(acc[1][1], av.y, wyy);
            fma2(acc[1][2], av.y, wzz); fma2(acc[1][3], av.y, www);
        }
        __syncthreads();                 // all As reads done before sg overlay

        // ---- stage gate pre-activations: 4 rows x 4 cols ----
#pragma unroll
        for (int p = 0; p < 2; p++) {
            float2 f0 = unpack2(acc[p][0]);
            float2 f1 = unpack2(acc[p][1]);
            float2 f2 = unpack2(acc[p][2]);
            float2 f3 = unpack2(acc[p][3]);
            *(float4*)&sg[(b4 + 2 * p + 0) * 68 + c4] =
                make_float4(f0.x, f1.x, f2.x, f3.x);
            *(float4*)&sg[(b4 + 2 * p + 1) * 68 + c4] =
                make_float4(f0.y, f1.y, f2.y, f3.y);
        }
        __syncthreads();

        // ---- LSTM pointwise: 512 (b,u) pairs / 128 threads ----
#pragma unroll
        for (int r = 0; r < 4; r++) {
            int pair = tid * 4 + r;
            int bb = pair >> 4;
            int u  = pair & 15;
            float pi = sg[bb * 68 + u]      + bias[u];
            float pf = sg[bb * 68 + 16 + u] + bias[16 + u];
            float pg = sg[bb * 68 + 32 + u] + bias[32 + u];
            float po = sg[bb * 68 + 48 + u] + bias[48 + u];
            float ig = fsigmoid(pi);
            float fg = fsigmoid(pf);
            float gg = ftanh(pg);
            float og = fsigmoid(po);
            float cv = fg * cs[bb * 16 + u] + ig * gg;
            cs[bb * 16 + u] = cv;
            float hv = og * ftanh(cv);
            __stcg(&hw[(mbase + bb) * HH + jbase + u], hv);
            if (ARCHIVE)
                __stcg(&g_h1[(size_t)((mbase + bb) * TT + t) * HH + jbase + u], hv);
        }

        // prefetch non-recurrent A rows for t+1 (disjoint from sg region)
        if (t + 1 < TT)
            stage_A<KIN>(as, HH / 32, K / 32, t + 1, mbase, nullptr, xin);

        group_barrier(grp);
    }
}

// ---------------- full model -----------------------------------------------
__global__ void __launch_bounds__(NTHR, 1)
lstm_persistent_kernel(const float* __restrict__ x,
                       const float* __restrict__ Wih0, const float* __restrict__ Whh0,
                       const float* __restrict__ bih0, const float* __restrict__ bhh0,
                       const float* __restrict__ Wih1, const float* __restrict__ Whh1,
                       const float* __restrict__ bih1, const float* __restrict__ bhh1,
                       const float* __restrict__ Wfc,  const float* __restrict__ bfc,
                       float* __restrict__ out) {
    run_layer<II, true >(x,    Wih0, Whh0, bih0, bhh0);
    run_layer<HH, false>(g_h1, Wih1, Whh1, bih1, bhh1);

    if ((blockIdx.x & 15) == 0) {
        int mbase = (blockIdx.x >> 4) * 32;
        for (int bb = threadIdx.x; bb < 32; bb += NTHR) {
            float s = bfc[0];
#pragma unroll 8
            for (int j = 0; j < HH; j++)
                s += __ldcg(&g_hbuf[0][(mbase + bb) * HH + j]) * Wfc[j];
            out[mbase + bb] = s;
        }
    }
}

// ---------------- harness entry --------------------------------------------
extern "C" void kernel_launch(void* const* d_in, const int* in_sizes, int n_in,
                              void* d_out, int out_size) {
    (void)in_sizes; (void)n_in; (void)out_size;
    const float* x    = (const float*)d_in[0];
    const float* Wih0 = (const float*)d_in[1];
    const float* Whh0 = (const float*)d_in[2];
    const float* bih0 = (const float*)d_in[3];
    const float* bhh0 = (const float*)d_in[4];
    const float* Wih1 = (const float*)d_in[5];
    const float* Whh1 = (const float*)d_in[6];
    const float* bih1 = (const float*)d_in[7];
    const float* bhh1 = (const float*)d_in[8];
    const float* Wfc  = (const float*)d_in[9];
    const float* bfc  = (const float*)d_in[10];

    // Layer-1 footprint: (512*68 + 512*36 + 512 + 64) floats = 215,296 B
    const int smem_bytes = (512 * 68 + 512 * 36 + 512 + 64) * 4;
    cudaFuncSetAttribute(lstm_persistent_kernel,
                         cudaFuncAttributeMaxDynamicSharedMemorySize, smem_bytes);

    lstm_persistent_kernel<<<GRID, NTHR, smem_bytes>>>(
        x, Wih0, Whh0, bih0, bhh0,
        Wih1, Whh1, bih1, bhh1,
        Wfc, bfc, (float*)d_out);
}

// round 10
// speedup vs baseline: 1.8212x; 1.1373x over previous
#include <cuda_runtime.h>

// 2-layer LSTM (B=256, T=512, I=64, H=256) + FC(H->1), fp32.
// Persistent kernel, 128 CTAs x 128 threads, CTA tile 32 batch x 16 units.
// Weights resident in smem. 4b x 4c FFMA2 tile, depth-2 software-pipelined.
// GEMM split: x-part before the group wait (skew absorption).
// One-way flag-based group synchronization (16-CTA groups).

#define BB   256
#define TT   512
#define II   64
#define HH   256

#define GRID 128
#define NTHR 128
#define GSIZE 16

typedef unsigned long long ull;

// ---------------- device globals (scratch) ---------------------------------
__device__ float g_hbuf[2][BB * HH];
__device__ float g_h1[(size_t)BB * TT * HH];
__device__ int          g_flag[8 * 32];    // 16 flags per group, 128B stride
__device__ ull          g_gen8[8 * 32];    // startup barrier only
__device__ unsigned int g_cnt8[8 * 32];

// ---------------- startup atomic barrier (replay-safe) ----------------------
__device__ __forceinline__ void group_barrier_atomic(int g) {
    __syncthreads();
    __threadfence();
    if (threadIdx.x == 0) {
        volatile ull* genp = &g_gen8[g * 32];
        ull my = *genp;
        unsigned prev = atomicAdd(&g_cnt8[g * 32], 1u);
        if (prev == GSIZE - 1u) {
            g_cnt8[g * 32] = 0u;
            __threadfence();
            atomicAdd((ull*)&g_gen8[g * 32], 1ULL);
        } else {
            while (*genp == my) __nanosleep(32);
        }
        __threadfence();
    }
    __syncthreads();
}

// ---------------- flag sync -------------------------------------------------
__device__ __forceinline__ void wait_group(int grp, int target) {
    if (threadIdx.x < GSIZE) {
        volatile int* f = &g_flag[grp * 32 + threadIdx.x];
        while (*f < target) { }
    }
    __syncthreads();
}
// publish: all CTA threads' prior stores ordered by syncthreads, then fence+flag
__device__ __forceinline__ void publish(int grp, int j, int epoch) {
    __syncthreads();
    if (threadIdx.x == 0) {
        __threadfence();
        *(volatile int*)&g_flag[grp * 32 + j] = epoch;
    }
}

// ---------------- packed f32x2 helpers -------------------------------------
__device__ __forceinline__ void fma2(ull& d, ull a, ull b) {
    asm("fma.rn.f32x2 %0, %1, %2, %0;" : "+l"(d) : "l"(a), "l"(b));
}
__device__ __forceinline__ ull pack2(float lo, float hi) {
    ull v;
    asm("mov.b64 %0, {%1, %2};" : "=l"(v) : "f"(lo), "f"(hi));
    return v;
}
__device__ __forceinline__ float2 unpack2(ull v) {
    float2 f;
    asm("mov.b64 {%0, %1}, %2;" : "=f"(f.x), "=f"(f.y) : "l"(v));
    return f;
}

// ---------------- activations ----------------------------------------------
__device__ __forceinline__ float fsigmoid(float x) {
    return 1.0f / (1.0f + __expf(-x));
}
__device__ __forceinline__ float ftanh(float x) {
    x = fminf(15.0f, fmaxf(-15.0f, x));
    float t = __expf(2.0f * x);
    return (t - 1.0f) / (t + 1.0f);
}

// Dynamic smem layout (floats), K = HH + KIN:
//   ws   [K][68]   weight slice, k-major (272B rows)
//   as   [K][36]   A tile ([h | x]), k-major, batch-contiguous
//   sg   [32][68]  gate pre-activations (own buffer now)
//   cs   [512], bias [64]
extern __shared__ float smbuf[];

// ---------------- A staging: chunks of 32 k-rows ----------------------------
template<int KIN>
__device__ __forceinline__ void stage_A(float* as, int c0, int c1, int t, int mbase,
                                        const float* __restrict__ hr,
                                        const float* __restrict__ xin) {
    const int tid = threadIdx.x;
    for (int c = c0; c < c1; c++) {
#pragma unroll
        for (int i = 0; i < 2; i++) {
            int idx = tid + i * NTHR;
            int bb  = idx >> 3;
            int k   = c * 32 + (idx & 7) * 4;
            const float* src;
            if (k < HH) src = hr + (mbase + bb) * HH + k;
            else {
                if (KIN == HH)
                    src = xin + ((size_t)(mbase + bb) * TT + t) * HH + (k - HH);
                else
                    src = xin + ((size_t)(mbase + bb) * TT + t) * II + (k - HH);
            }
            float4 a = __ldcg((const float4*)src);
            as[(k + 0) * 36 + bb] = a.x;
            as[(k + 1) * 36 + bb] = a.y;
            as[(k + 2) * 36 + bb] = a.z;
            as[(k + 3) * 36 + bb] = a.w;
        }
    }
}

// ---------------- GEMM over k-range [k0, k1), depth-2 pipelined -------------
#define GMATH(AV, W) do {                                                     \
    ull wxx = pack2((W).x, (W).x), wyy = pack2((W).y, (W).y);                 \
    ull wzz = pack2((W).z, (W).z), www = pack2((W).w, (W).w);                 \
    fma2(acc[0][0], (AV).x, wxx); fma2(acc[0][1], (AV).x, wyy);               \
    fma2(acc[0][2], (AV).x, wzz); fma2(acc[0][3], (AV).x, www);               \
    fma2(acc[1][0], (AV).y, wxx); fma2(acc[1][1], (AV).y, wyy);               \
    fma2(acc[1][2], (AV).y, wzz); fma2(acc[1][3], (AV).y, www);               \
} while (0)

__device__ __forceinline__ void gemm_range(ull (&acc)[2][4],
                                           const float* __restrict__ as,
                                           const float* __restrict__ ws,
                                           int k0, int k1, int b4, int c4) {
    const float* ap = as + k0 * 36 + b4;
    const float* wp = ws + k0 * 68 + c4;
    const int n = k1 - k0;
    ulonglong2 av0 = *(const ulonglong2*)ap;
    float4     w0  = *(const float4*)wp;
    ulonglong2 av1 = *(const ulonglong2*)(ap + 36);
    float4     w1  = *(const float4*)(wp + 68);
    ap += 72; wp += 136;
#pragma unroll 8
    for (int kk = 0; kk < n - 2; kk++) {
        ulonglong2 av2 = *(const ulonglong2*)ap;
        float4     w2  = *(const float4*)wp;
        ap += 36; wp += 68;
        GMATH(av0, w0);
        av0 = av1; w0 = w1;
        av1 = av2; w1 = w2;
    }
    GMATH(av0, w0);
    GMATH(av1, w1);
}

// ---------------- one LSTM layer -------------------------------------------
template<int KIN, bool ARCHIVE>
__device__ void run_layer(int base, const float* __restrict__ xin,
                          const float* __restrict__ Wih,
                          const float* __restrict__ Whh,
                          const float* __restrict__ bih,
                          const float* __restrict__ bhh) {
    constexpr int K = HH + KIN;
    float* ws   = smbuf;                   // [K][68]
    float* as   = smbuf + K * 68;          // [K][36]
    float* sg   = as + K * 36;             // [32][68]
    float* cs   = sg + 32 * 68;            // [512]
    float* bias = cs + 512;                // [64]

    const int tid   = threadIdx.x;
    const int grp   = blockIdx.x >> 4;
    const int jj    = blockIdx.x & 15;
    const int mbase = grp * 32;
    const int jbase = jj * 16;

    // ---- layer entry gate (L1 waits for all of L0) ----
    wait_group(grp, base);

    // ---- init: weight slice -> smem, zero c / h(-1), biases ----
    constexpr int K4 = K / 4;
    for (int idx = tid; idx < 64 * K4; idx += NTHR) {
        int cc = idx / K4;
        int k  = (idx - cc * K4) * 4;
        int gate = cc >> 4, u = cc & 15;
        int grow = gate * HH + jbase + u;
        const float* src = (k < HH) ? (Whh + grow * HH + k)
                                    : (Wih + grow * KIN + k - HH);
        float4 w = *(const float4*)src;
        ws[(k + 0) * 68 + cc] = w.x;
        ws[(k + 1) * 68 + cc] = w.y;
        ws[(k + 2) * 68 + cc] = w.z;
        ws[(k + 3) * 68 + cc] = w.w;
    }
    for (int idx = tid; idx < 512; idx += NTHR) {
        cs[idx] = 0.0f;
        int bb = idx >> 4, u = idx & 15;
        __stcg(&g_hbuf[0][(mbase + bb) * HH + jbase + u], 0.0f);
    }
    if (tid < 64) {
        int gate = tid >> 4, u = tid & 15;
        int grow = gate * HH + jbase + u;
        bias[tid] = bih[grow] + bhh[grow];
    }
    publish(grp, jj, base + 1);            // h(-1) zeros visible group-wide

    // prologue: stage x-part for t=0, make it CTA-visible
    stage_A<KIN>(as, HH / 32, K / 32, 0, mbase, nullptr, xin);
    __syncthreads();

    const int b4 = (tid & 7) * 4;
    const int c4 = (tid >> 3) * 4;

    for (int t = 0; t < TT; t++) {
        const float* hr = g_hbuf[t & 1];
        float*       hw = g_hbuf[(t & 1) ^ 1];

        ull acc[2][4];
#pragma unroll
        for (int p = 0; p < 2; p++)
#pragma unroll
            for (int c = 0; c < 4; c++) acc[p][c] = 0ULL;

        // ---- x-part GEMM first: independent of h(t-1), absorbs group skew
        gemm_range(acc, as, ws, HH, K, b4, c4);

        // ---- wait for group h(t-1), stage it, finish GEMM ----
        wait_group(grp, base + 1 + t);
        stage_A<KIN>(as, 0, HH / 32, t, mbase, hr, xin);
        __syncthreads();
        gemm_range(acc, as, ws, 0, HH, b4, c4);

        // ---- stage gate pre-activations (sg is its own buffer) ----
#pragma unroll
        for (int p = 0; p < 2; p++) {
            float2 f0 = unpack2(acc[p][0]);
            float2 f1 = unpack2(acc[p][1]);
            float2 f2 = unpack2(acc[p][2]);
            float2 f3 = unpack2(acc[p][3]);
            *(float4*)&sg[(b4 + 2 * p + 0) * 68 + c4] =
                make_float4(f0.x, f1.x, f2.x, f3.x);
            *(float4*)&sg[(b4 + 2 * p + 1) * 68 + c4] =
                make_float4(f0.y, f1.y, f2.y, f3.y);
        }
        __syncthreads();   // sg visible; all 'as' reads of this step done

        // ---- LSTM pointwise: 512 (b,u) pairs / 128 threads ----
#pragma unroll
        for (int r = 0; r < 4; r++) {
            int pair = tid * 4 + r;
            int bb = pair >> 4;
            int u  = pair & 15;
            float pi = sg[bb * 68 + u]      + bias[u];
            float pf = sg[bb * 68 + 16 + u] + bias[16 + u];
            float pg = sg[bb * 68 + 32 + u] + bias[32 + u];
            float po = sg[bb * 68 + 48 + u] + bias[48 + u];
            float ig = fsigmoid(pi);
            float fg = fsigmoid(pf);
            float gg = ftanh(pg);
            float og = fsigmoid(po);
            float cv = fg * cs[bb * 16 + u] + ig * gg;
            cs[bb * 16 + u] = cv;
            float hv = og * ftanh(cv);
            __stcg(&hw[(mbase + bb) * HH + jbase + u], hv);
            if (ARCHIVE)
                __stcg(&g_h1[(size_t)((mbase + bb) * TT + t) * HH + jbase + u], hv);
        }

        // prefetch x-part for t+1 (safe: post-sync, all 'as' reads done)
        if (t + 1 < TT)
            stage_A<KIN>(as, HH / 32, K / 32, t + 1, mbase, nullptr, xin);

        publish(grp, jj, base + 2 + t);    // h(t) + step-t reads complete
    }
}

// ---------------- full model -----------------------------------------------
__global__ void __launch_bounds__(NTHR, 1)
lstm_persistent_kernel(const float* __restrict__ x,
                       const float* __restrict__ Wih0, const float* __restrict__ Whh0,
                       const float* __restrict__ bih0, const float* __restrict__ bhh0,
                       const float* __restrict__ Wih1, const float* __restrict__ Whh1,
                       const float* __restrict__ bih1, const float* __restrict__ bhh1,
                       const float* __restrict__ Wfc,  const float* __restrict__ bfc,
                       float* __restrict__ out) {
    const int grp = blockIdx.x >> 4;
    const int jj  = blockIdx.x & 15;

    // replay-safe flag reset
    if (threadIdx.x == 0)
        *(volatile int*)&g_flag[grp * 32 + jj] = 0;
    group_barrier_atomic(grp);

    run_layer<II, true >(0,         x,    Wih0, Whh0, bih0, bhh0);  // epochs 1..513
    run_layer<HH, false>(TT + 1,    g_h1, Wih1, Whh1, bih1, bhh1);  // epochs 514..1026

    // FC head: one CTA per group; final h2 in g_hbuf[0]
    if (jj == 0) {
        wait_group(grp, 2 * TT + 2);       // = 1026
        int mbase = grp * 32;
        for (int bb = threadIdx.x; bb < 32; bb += NTHR) {
            float s = bfc[0];
#pragma unroll 8
            for (int j = 0; j < HH; j++)
                s += __ldcg(&g_hbuf[0][(mbase + bb) * HH + j]) * Wfc[j];
            out[mbase + bb] = s;
        }
    }
}

// ---------------- harness entry --------------------------------------------
extern "C" void kernel_launch(void* const* d_in, const int* in_sizes, int n_in,
                              void* d_out, int out_size) {
    (void)in_sizes; (void)n_in; (void)out_size;
    const float* x    = (const float*)d_in[0];
    const float* Wih0 = (const float*)d_in[1];
    const float* Whh0 = (const float*)d_in[2];
    const float* bih0 = (const float*)d_in[3];
    const float* bhh0 = (const float*)d_in[4];
    const float* Wih1 = (const float*)d_in[5];
    const float* Whh1 = (const float*)d_in[6];
    const float* bih1 = (const float*)d_in[7];
    const float* bhh1 = (const float*)d_in[8];
    const float* Wfc  = (const float*)d_in[9];
    const float* bfc  = (const float*)d_in[10];

    // Layer-1 footprint: 512*68 + 512*36 + 32*68 + 512 + 64 = 56000 floats
    const int smem_bytes = 56000 * 4;      // 224,000 B  (< 227 KB cap)
    cudaFuncSetAttribute(lstm_persistent_kernel,
                         cudaFuncAttributeMaxDynamicSharedMemorySize, smem_bytes);

    lstm_persistent_kernel<<<GRID, NTHR, smem_bytes>>>(
        x, Wih0, Whh0, bih0, bhh0,
        Wih1, Whh1, bih1, bhh1,
        Wfc, bfc, (float*)d_out);
}

// round 11
// speedup vs baseline: 2.1432x; 1.1768x over previous
#include <cuda_runtime.h>

// 2-layer LSTM (B=256, T=512, I=64, H=256) + FC(H->1), fp32.
// Persistent kernel, 128 CTAs x 256 threads, CTA tile 32 batch x 16 units.
// Weights resident in smem. 4b x 4c FFMA2 tile, depth-2 pipelined.
// K split across two warp-sets (2 warps/SMSP) + packed-f32x2 reduction.
// x-part GEMM before the group wait; one-way flag group sync.

#define BB   256
#define TT   512
#define II   64
#define HH   256

#define GRID 128
#define NTHR 256
#define GSIZE 16

typedef unsigned long long ull;

// ---------------- device globals (scratch) ---------------------------------
__device__ float g_hbuf[2][BB * HH];
__device__ float g_h1[(size_t)BB * TT * HH];
__device__ int          g_flag[8 * 32];
__device__ ull          g_gen8[8 * 32];
__device__ unsigned int g_cnt8[8 * 32];

// ---------------- startup atomic barrier (replay-safe) ----------------------
__device__ __forceinline__ void group_barrier_atomic(int g) {
    __syncthreads();
    __threadfence();
    if (threadIdx.x == 0) {
        volatile ull* genp = &g_gen8[g * 32];
        ull my = *genp;
        unsigned prev = atomicAdd(&g_cnt8[g * 32], 1u);
        if (prev == GSIZE - 1u) {
            g_cnt8[g * 32] = 0u;
            __threadfence();
            atomicAdd((ull*)&g_gen8[g * 32], 1ULL);
        } else {
            while (*genp == my) __nanosleep(32);
        }
        __threadfence();
    }
    __syncthreads();
}

// ---------------- flag sync -------------------------------------------------
__device__ __forceinline__ void wait_group(int grp, int target) {
    if (threadIdx.x < GSIZE) {
        volatile int* f = &g_flag[grp * 32 + threadIdx.x];
        while (*f < target) { }
    }
    __syncthreads();
}
__device__ __forceinline__ void publish(int grp, int j, int epoch) {
    __syncthreads();
    if (threadIdx.x == 0) {
        __threadfence();
        *(volatile int*)&g_flag[grp * 32 + j] = epoch;
    }
}

// ---------------- packed f32x2 helpers -------------------------------------
__device__ __forceinline__ void fma2(ull& d, ull a, ull b) {
    asm("fma.rn.f32x2 %0, %1, %2, %0;" : "+l"(d) : "l"(a), "l"(b));
}
__device__ __forceinline__ ull add2(ull a, ull b) {
    ull r;
    asm("add.rn.f32x2 %0, %1, %2;" : "=l"(r) : "l"(a), "l"(b));
    return r;
}
__device__ __forceinline__ ull pack2(float lo, float hi) {
    ull v;
    asm("mov.b64 %0, {%1, %2};" : "=l"(v) : "f"(lo), "f"(hi));
    return v;
}
__device__ __forceinline__ float2 unpack2(ull v) {
    float2 f;
    asm("mov.b64 {%0, %1}, %2;" : "=f"(f.x), "=f"(f.y) : "l"(v));
    return f;
}

// ---------------- activations ----------------------------------------------
__device__ __forceinline__ float fsigmoid(float x) {
    return 1.0f / (1.0f + __expf(-x));
}
__device__ __forceinline__ float ftanh(float x) {
    x = fminf(15.0f, fmaxf(-15.0f, x));
    float t = __expf(2.0f * x);
    return (t - 1.0f) / (t + 1.0f);
}

// Dynamic smem (floats), K = HH + KIN:
//   ws   [K][68]       weight slice, k-major (272B rows)
//   as   [K][36]+pad   A tile ([h | x]); x-rows region doubles as 'red'
//   sg   [32][68]      gate pre-activations
//   cs   [512], bias [64]
extern __shared__ float smbuf[];

// ---------------- A staging: chunks of 32 k-rows (256 threads) --------------
template<int KIN>
__device__ __forceinline__ void stage_A(float* as, int c0, int c1, int t, int mbase,
                                        const float* __restrict__ hr,
                                        const float* __restrict__ xin) {
    const int bb  = threadIdx.x >> 3;          // 0..31
    const int kof = (threadIdx.x & 7) * 4;
    for (int c = c0; c < c1; c++) {
        int k = c * 32 + kof;
        const float* src;
        if (k < HH) src = hr + (mbase + bb) * HH + k;
        else {
            if (KIN == HH)
                src = xin + ((size_t)(mbase + bb) * TT + t) * HH + (k - HH);
            else
                src = xin + ((size_t)(mbase + bb) * TT + t) * II + (k - HH);
        }
        float4 a = __ldcg((const float4*)src);
        as[(k + 0) * 36 + bb] = a.x;
        as[(k + 1) * 36 + bb] = a.y;
        as[(k + 2) * 36 + bb] = a.z;
        as[(k + 3) * 36 + bb] = a.w;
    }
}

// ---------------- GEMM over k-range [k0, k1), depth-2 pipelined -------------
#define GMATH(AV, W) do {                                                     \
    ull wxx = pack2((W).x, (W).x), wyy = pack2((W).y, (W).y);                 \
    ull wzz = pack2((W).z, (W).z), www = pack2((W).w, (W).w);                 \
    fma2(acc[0][0], (AV).x, wxx); fma2(acc[0][1], (AV).x, wyy);               \
    fma2(acc[0][2], (AV).x, wzz); fma2(acc[0][3], (AV).x, www);               \
    fma2(acc[1][0], (AV).y, wxx); fma2(acc[1][1], (AV).y, wyy);               \
    fma2(acc[1][2], (AV).y, wzz); fma2(acc[1][3], (AV).y, www);               \
} while (0)

__device__ __forceinline__ void gemm_range(ull (&acc)[2][4],
                                           const float* __restrict__ as,
                                           const float* __restrict__ ws,
                                           int k0, int k1, int b4, int c4) {
    const float* ap = as + k0 * 36 + b4;
    const float* wp = ws + k0 * 68 + c4;
    const int n = k1 - k0;
    ulonglong2 av0 = *(const ulonglong2*)ap;
    float4     w0  = *(const float4*)wp;
    ulonglong2 av1 = *(const ulonglong2*)(ap + 36);
    float4     w1  = *(const float4*)(wp + 68);
    ap += 72; wp += 136;
#pragma unroll 8
    for (int kk = 0; kk < n - 2; kk++) {
        ulonglong2 av2 = *(const ulonglong2*)ap;
        float4     w2  = *(const float4*)wp;
        ap += 36; wp += 68;
        GMATH(av0, w0);
        av0 = av1; w0 = w1;
        av1 = av2; w1 = w2;
    }
    GMATH(av0, w0);
    GMATH(av1, w1);
}

// ---------------- one LSTM layer -------------------------------------------
template<int KIN, bool ARCHIVE>
__device__ void run_layer(int base, const float* __restrict__ xin,
                          const float* __restrict__ Wih,
                          const float* __restrict__ Whh,
                          const float* __restrict__ bih,
                          const float* __restrict__ bhh) {
    constexpr int K = HH + KIN;
    float* ws   = smbuf;                       // [K][68]
    float* as   = smbuf + K * 68;              // [K][36] (+pad)
    float* sg   = as + K * 36 + 320;           // [32][68]
    float* cs   = sg + 32 * 68;                // [512]
    float* bias = cs + 512;                    // [64]
    ull*   red  = (ull*)(as + HH * 36);        // overlays x-rows: 128*10 ull

    const int tid   = threadIdx.x;
    const int grp   = blockIdx.x >> 4;
    const int jj    = blockIdx.x & 15;
    const int mbase = grp * 32;
    const int jbase = jj * 16;

    wait_group(grp, base);                     // layer entry gate

    // ---- init: weight slice -> smem, zero c / h(-1), biases ----
    constexpr int K4 = K / 4;
    for (int idx = tid; idx < 64 * K4; idx += NTHR) {
        int cc = idx / K4;
        int k  = (idx - cc * K4) * 4;
        int gate = cc >> 4, u = cc & 15;
        int grow = gate * HH + jbase + u;
        const float* src = (k < HH) ? (Whh + grow * HH + k)
                                    : (Wih + grow * KIN + k - HH);
        float4 w = *(const float4*)src;
        ws[(k + 0) * 68 + cc] = w.x;
        ws[(k + 1) * 68 + cc] = w.y;
        ws[(k + 2) * 68 + cc] = w.z;
        ws[(k + 3) * 68 + cc] = w.w;
    }
    for (int idx = tid; idx < 512; idx += NTHR) {
        cs[idx] = 0.0f;
        int bb = idx >> 4, u = idx & 15;
        __stcg(&g_hbuf[0][(mbase + bb) * HH + jbase + u], 0.0f);
    }
    if (tid < 64) {
        int gate = tid >> 4, u = tid & 15;
        int grow = gate * HH + jbase + u;
        bias[tid] = bih[grow] + bhh[grow];
    }
    publish(grp, jj, base + 1);

    // prologue: stage x-part for t=0
    stage_A<KIN>(as, HH / 32, K / 32, 0, mbase, nullptr, xin);
    __syncthreads();

    const int sset = tid >> 7;                 // warp-set 0/1
    const int stid = tid & 127;
    const int b4 = (stid & 7) * 4;
    const int c4 = (stid >> 3) * 4;
    constexpr int XH = KIN / 2;
    const int x0 = HH + sset * XH, x1 = x0 + XH;
    const int h0 = sset * (HH / 2), h1e = h0 + HH / 2;

    for (int t = 0; t < TT; t++) {
        const float* hr = g_hbuf[t & 1];
        float*       hw = g_hbuf[(t & 1) ^ 1];

        ull acc[2][4];
#pragma unroll
        for (int p = 0; p < 2; p++)
#pragma unroll
            for (int c = 0; c < 4; c++) acc[p][c] = 0ULL;

        // x-part (independent of h(t-1)) — absorbs group skew
        gemm_range(acc, as, ws, x0, x1, b4, c4);

        // wait for h(t-1), stage it (all 256 threads), finish this set's half
        wait_group(grp, base + 1 + t);
        stage_A<KIN>(as, 0, HH / 32, t, mbase, hr, xin);
        __syncthreads();
        gemm_range(acc, as, ws, h0, h1e, b4, c4);

        // ---- cross-set reduction (red overlays x-rows; races excluded by
        //      the wait_group sync before this point and the syncs below) ----
        if (sset == 1) {
#pragma unroll
            for (int p = 0; p < 2; p++)
#pragma unroll
                for (int c = 0; c < 4; c++)
                    red[stid * 10 + p * 4 + c] = acc[p][c];
        }
        __syncthreads();
        if (sset == 0) {
#pragma unroll
            for (int p = 0; p < 2; p++)
#pragma unroll
                for (int c = 0; c < 4; c++)
                    acc[p][c] = add2(acc[p][c], red[stid * 10 + p * 4 + c]);
            // stage gate pre-activations
#pragma unroll
            for (int p = 0; p < 2; p++) {
                float2 f0 = unpack2(acc[p][0]);
                float2 f1 = unpack2(acc[p][1]);
                float2 f2 = unpack2(acc[p][2]);
                float2 f3 = unpack2(acc[p][3]);
                *(float4*)&sg[(b4 + 2 * p + 0) * 68 + c4] =
                    make_float4(f0.x, f1.x, f2.x, f3.x);
                *(float4*)&sg[(b4 + 2 * p + 1) * 68 + c4] =
                    make_float4(f0.y, f1.y, f2.y, f3.y);
            }
        }
        __syncthreads();

        // ---- LSTM pointwise: 512 (b,u) pairs / 256 threads ----
#pragma unroll
        for (int r = 0; r < 2; r++) {
            int pair = tid * 2 + r;
            int bb = pair >> 4;
            int u  = pair & 15;
            float pi = sg[bb * 68 + u]      + bias[u];
            float pf = sg[bb * 68 + 16 + u] + bias[16 + u];
            float pg = sg[bb * 68 + 32 + u] + bias[32 + u];
            float po = sg[bb * 68 + 48 + u] + bias[48 + u];
            float ig = fsigmoid(pi);
            float fg = fsigmoid(pf);
            float gg = ftanh(pg);
            float og = fsigmoid(po);
            float cv = fg * cs[bb * 16 + u] + ig * gg;
            cs[bb * 16 + u] = cv;
            float hv = og * ftanh(cv);
            __stcg(&hw[(mbase + bb) * HH + jbase + u], hv);
            if (ARCHIVE)
                __stcg(&g_h1[(size_t)((mbase + bb) * TT + t) * HH + jbase + u], hv);
        }

        // prefetch x-part for t+1 (after red reads: protected by sync above)
        if (t + 1 < TT)
            stage_A<KIN>(as, HH / 32, K / 32, t + 1, mbase, nullptr, xin);

        publish(grp, jj, base + 2 + t);
    }
}

// ---------------- full model -----------------------------------------------
__global__ void __launch_bounds__(NTHR, 1)
lstm_persistent_kernel(const float* __restrict__ x,
                       const float* __restrict__ Wih0, const float* __restrict__ Whh0,
                       const float* __restrict__ bih0, const float* __restrict__ bhh0,
                       const float* __restrict__ Wih1, const float* __restrict__ Whh1,
                       const float* __restrict__ bih1, const float* __restrict__ bhh1,
                       const float* __restrict__ Wfc,  const float* __restrict__ bfc,
                       float* __restrict__ out) {
    const int grp = blockIdx.x >> 4;
    const int jj  = blockIdx.x & 15;

    if (threadIdx.x == 0)
        *(volatile int*)&g_flag[grp * 32 + jj] = 0;
    group_barrier_atomic(grp);

    run_layer<II, true >(0,      x,    Wih0, Whh0, bih0, bhh0);  // epochs 1..513
    run_layer<HH, false>(TT + 1, g_h1, Wih1, Whh1, bih1, bhh1);  // 514..1026

    if (jj == 0) {
        wait_group(grp, 2 * TT + 2);
        int mbase = grp * 32;
        for (int bb = threadIdx.x; bb < 32; bb += NTHR) {
            float s = bfc[0];
#pragma unroll 8
            for (int j = 0; j < HH; j++)
                s += __ldcg(&g_hbuf[0][(mbase + bb) * HH + j]) * Wfc[j];
            out[mbase + bb] = s;
        }
    }
}

// ---------------- harness entry --------------------------------------------
extern "C" void kernel_launch(void* const* d_in, const int* in_sizes, int n_in,
                              void* d_out, int out_size) {
    (void)in_sizes; (void)n_in; (void)out_size;
    const float* x    = (const float*)d_in[0];
    const float* Wih0 = (const float*)d_in[1];
    const float* Whh0 = (const float*)d_in[2];
    const float* bih0 = (const float*)d_in[3];
    const float* bhh0 = (const float*)d_in[4];
    const float* Wih1 = (const float*)d_in[5];
    const float* Whh1 = (const float*)d_in[6];
    const float* bih1 = (const float*)d_in[7];
    const float* bhh1 = (const float*)d_in[8];
    const float* Wfc  = (const float*)d_in[9];
    const float* bfc  = (const float*)d_in[10];

    // L1 footprint: 512*68 + 512*36 + 320 + 32*68 + 512 + 64 = 56320 floats
    const int smem_bytes = 56320 * 4;          // 225,280 B
    cudaFuncSetAttribute(lstm_persistent_kernel,
                         cudaFuncAttributeMaxDynamicSharedMemorySize, smem_bytes);

    lstm_persistent_kernel<<<GRID, NTHR, smem_bytes>>>(
        x, Wih0, Whh0, bih0, bhh0,
        Wih1, Whh1, bih1, bhh1,
        Wfc, bfc, (float*)d_out);
}

// round 13
// speedup vs baseline: 2.1474x; 1.0020x over previous
#include <cuda_runtime.h>

// 2-layer LSTM (B=256, T=512, I=64, H=256) + FC(H->1), fp32.
// Persistent kernel, 128 CTAs x 256 threads, CTA tile 32 batch x 16 units.
// Weights resident in smem. 4b x 4c FFMA2 tile, depth-2 pipelined.
// K split across two warp-sets (2 warps/SMSP) + packed-f32x2 reduction.
// x-part GEMM before the group wait; one-way flag group sync.

#define BB   256
#define TT   512
#define II   64
#define HH   256

#define GRID 128
#define NTHR 256
#define GSIZE 16

typedef unsigned long long ull;

// ---------------- device globals (scratch) ---------------------------------
__device__ float g_hbuf[2][BB * HH];
__device__ float g_h1[(size_t)BB * TT * HH];
__device__ int          g_flag[8 * 32];
__device__ ull          g_gen8[8 * 32];
__device__ unsigned int g_cnt8[8 * 32];

// ---------------- startup atomic barrier (replay-safe) ----------------------
__device__ __forceinline__ void group_barrier_atomic(int g) {
    __syncthreads();
    __threadfence();
    if (threadIdx.x == 0) {
        volatile ull* genp = &g_gen8[g * 32];
        ull my = *genp;
        unsigned prev = atomicAdd(&g_cnt8[g * 32], 1u);
        if (prev == GSIZE - 1u) {
            g_cnt8[g * 32] = 0u;
            __threadfence();
            atomicAdd((ull*)&g_gen8[g * 32], 1ULL);
        } else {
            while (*genp == my) __nanosleep(32);
        }
        __threadfence();
    }
    __syncthreads();
}

// ---------------- flag sync -------------------------------------------------
__device__ __forceinline__ void wait_group(int grp, int target) {
    if (threadIdx.x < GSIZE) {
        volatile int* f = &g_flag[grp * 32 + threadIdx.x];
        while (*f < target) { }
    }
    __syncthreads();
}
__device__ __forceinline__ void publish(int grp, int j, int epoch) {
    __syncthreads();
    if (threadIdx.x == 0) {
        __threadfence();
        *(volatile int*)&g_flag[grp * 32 + j] = epoch;
    }
}

// ---------------- packed f32x2 helpers -------------------------------------
__device__ __forceinline__ void fma2(ull& d, ull a, ull b) {
    asm("fma.rn.f32x2 %0, %1, %2, %0;" : "+l"(d) : "l"(a), "l"(b));
}
__device__ __forceinline__ ull add2(ull a, ull b) {
    ull r;
    asm("add.rn.f32x2 %0, %1, %2;" : "=l"(r) : "l"(a), "l"(b));
    return r;
}
__device__ __forceinline__ ull pack2(float lo, float hi) {
    ull v;
    asm("mov.b64 %0, {%1, %2};" : "=l"(v) : "f"(lo), "f"(hi));
    return v;
}
__device__ __forceinline__ float2 unpack2(ull v) {
    float2 f;
    asm("mov.b64 {%0, %1}, %2;" : "=f"(f.x), "=f"(f.y) : "l"(v));
    return f;
}

// ---------------- activations ----------------------------------------------
__device__ __forceinline__ float fsigmoid(float x) {
    return 1.0f / (1.0f + __expf(-x));
}
__device__ __forceinline__ float ftanh(float x) {
    x = fminf(15.0f, fmaxf(-15.0f, x));
    float t = __expf(2.0f * x);
    return (t - 1.0f) / (t + 1.0f);
}

// Dynamic smem (floats), K = HH + KIN:
//   ws   [K][68]       weight slice, k-major (272B rows)
//   as   [K][36]+pad   A tile ([h | x]); x-rows region doubles as 'red'
//   sg   [32][68]      gate pre-activations
//   cs   [512], bias [64]
extern __shared__ float smbuf[];

// ---------------- A staging: chunks of 32 k-rows (256 threads) --------------
template<int KIN>
__device__ __forceinline__ void stage_A(float* as, int c0, int c1, int t, int mbase,
                                        const float* __restrict__ hr,
                                        const float* __restrict__ xin) {
    const int bb  = threadIdx.x >> 3;          // 0..31
    const int kof = (threadIdx.x & 7) * 4;
    for (int c = c0; c < c1; c++) {
        int k = c * 32 + kof;
        const float* src;
        if (k < HH) src = hr + (mbase + bb) * HH + k;
        else {
            if (KIN == HH)
                src = xin + ((size_t)(mbase + bb) * TT + t) * HH + (k - HH);
            else
                src = xin + ((size_t)(mbase + bb) * TT + t) * II + (k - HH);
        }
        float4 a = __ldcg((const float4*)src);
        as[(k + 0) * 36 + bb] = a.x;
        as[(k + 1) * 36 + bb] = a.y;
        as[(k + 2) * 36 + bb] = a.z;
        as[(k + 3) * 36 + bb] = a.w;
    }
}

// ---------------- GEMM over k-range [k0, k1), depth-2 pipelined -------------
#define GMATH(AV, W) do {                                                     \
    ull wxx = pack2((W).x, (W).x), wyy = pack2((W).y, (W).y);                 \
    ull wzz = pack2((W).z, (W).z), www = pack2((W).w, (W).w);                 \
    fma2(acc[0][0], (AV).x, wxx); fma2(acc[0][1], (AV).x, wyy);               \
    fma2(acc[0][2], (AV).x, wzz); fma2(acc[0][3], (AV).x, www);               \
    fma2(acc[1][0], (AV).y, wxx); fma2(acc[1][1], (AV).y, wyy);               \
    fma2(acc[1][2], (AV).y, wzz); fma2(acc[1][3], (AV).y, www);               \
} while (0)

__device__ __forceinline__ void gemm_range(ull (&acc)[2][4],
                                           const float* __restrict__ as,
                                           const float* __restrict__ ws,
                                           int k0, int k1, int b4, int c4) {
    const float* ap = as + k0 * 36 + b4;
    const float* wp = ws + k0 * 68 + c4;
    const int n = k1 - k0;
    ulonglong2 av0 = *(const ulonglong2*)ap;
    float4     w0  = *(const float4*)wp;
    ulonglong2 av1 = *(const ulonglong2*)(ap + 36);
    float4     w1  = *(const float4*)(wp + 68);
    ap += 72; wp += 136;
#pragma unroll 8
    for (int kk = 0; kk < n - 2; kk++) {
        ulonglong2 av2 = *(const ulonglong2*)ap;
        float4     w2  = *(const float4*)wp;
        ap += 36; wp += 68;
        GMATH(av0, w0);
        av0 = av1; w0 = w1;
        av1 = av2; w1 = w2;
    }
    GMATH(av0, w0);
    GMATH(av1, w1);
}

// ---------------- one LSTM layer -------------------------------------------
template<int KIN, bool ARCHIVE>
__device__ void run_layer(int base, const float* __restrict__ xin,
                          const float* __restrict__ Wih,
                          const float* __restrict__ Whh,
                          const float* __restrict__ bih,
                          const float* __restrict__ bhh) {
    constexpr int K = HH + KIN;
    float* ws   = smbuf;                       // [K][68]
    float* as   = smbuf + K * 68;              // [K][36] (+pad)
    float* sg   = as + K * 36 + 320;           // [32][68]
    float* cs   = sg + 32 * 68;                // [512]
    float* bias = cs + 512;                    // [64]
    ull*   red  = (ull*)(as + HH * 36);        // overlays x-rows: 128*10 ull

    const int tid   = threadIdx.x;
    const int grp   = blockIdx.x >> 4;
    const int jj    = blockIdx.x & 15;
    const int mbase = grp * 32;
    const int jbase = jj * 16;

    wait_group(grp, base);                     // layer entry gate

    // ---- init: weight slice -> smem, zero c / h(-1), biases ----
    constexpr int K4 = K / 4;
    for (int idx = tid; idx < 64 * K4; idx += NTHR) {
        int cc = idx / K4;
        int k  = (idx - cc * K4) * 4;
        int gate = cc >> 4, u = cc & 15;
        int grow = gate * HH + jbase + u;
        const float* src = (k < HH) ? (Whh + grow * HH + k)
                                    : (Wih + grow * KIN + k - HH);
        float4 w = *(const float4*)src;
        ws[(k + 0) * 68 + cc] = w.x;
        ws[(k + 1) * 68 + cc] = w.y;
        ws[(k + 2) * 68 + cc] = w.z;
        ws[(k + 3) * 68 + cc] = w.w;
    }
    for (int idx = tid; idx < 512; idx += NTHR) {
        cs[idx] = 0.0f;
        int bb = idx >> 4, u = idx & 15;
        __stcg(&g_hbuf[0][(mbase + bb) * HH + jbase + u], 0.0f);
    }
    if (tid < 64) {
        int gate = tid >> 4, u = tid & 15;
        int grow = gate * HH + jbase + u;
        bias[tid] = bih[grow] + bhh[grow];
    }
    publish(grp, jj, base + 1);

    // prologue: stage x-part for t=0
    stage_A<KIN>(as, HH / 32, K / 32, 0, mbase, nullptr, xin);
    __syncthreads();

    const int sset = tid >> 7;                 // warp-set 0/1
    const int stid = tid & 127;
    const int b4 = (stid & 7) * 4;
    const int c4 = (stid >> 3) * 4;
    constexpr int XH = KIN / 2;
    const int x0 = HH + sset * XH, x1 = x0 + XH;
    const int h0 = sset * (HH / 2), h1e = h0 + HH / 2;

    for (int t = 0; t < TT; t++) {
        const float* hr = g_hbuf[t & 1];
        float*       hw = g_hbuf[(t & 1) ^ 1];

        ull acc[2][4];
#pragma unroll
        for (int p = 0; p < 2; p++)
#pragma unroll
            for (int c = 0; c < 4; c++) acc[p][c] = 0ULL;

        // x-part (independent of h(t-1)) — absorbs group skew
        gemm_range(acc, as, ws, x0, x1, b4, c4);

        // wait for h(t-1), stage it (all 256 threads), finish this set's half
        wait_group(grp, base + 1 + t);
        stage_A<KIN>(as, 0, HH / 32, t, mbase, hr, xin);
        __syncthreads();
        gemm_range(acc, as, ws, h0, h1e, b4, c4);

        // ---- cross-set reduction (red overlays x-rows; races excluded by
        //      the wait_group sync before this point and the syncs below) ----
        if (sset == 1) {
#pragma unroll
            for (int p = 0; p < 2; p++)
#pragma unroll
                for (int c = 0; c < 4; c++)
                    red[stid * 10 + p * 4 + c] = acc[p][c];
        }
        __syncthreads();
        if (sset == 0) {
#pragma unroll
            for (int p = 0; p < 2; p++)
#pragma unroll
                for (int c = 0; c < 4; c++)
                    acc[p][c] = add2(acc[p][c], red[stid * 10 + p * 4 + c]);
            // stage gate pre-activations
#pragma unroll
            for (int p = 0; p < 2; p++) {
                float2 f0 = unpack2(acc[p][0]);
                float2 f1 = unpack2(acc[p][1]);
                float2 f2 = unpack2(acc[p][2]);
                float2 f3 = unpack2(acc[p][3]);
                *(float4*)&sg[(b4 + 2 * p + 0) * 68 + c4] =
                    make_float4(f0.x, f1.x, f2.x, f3.x);
                *(float4*)&sg[(b4 + 2 * p + 1) * 68 + c4] =
                    make_float4(f0.y, f1.y, f2.y, f3.y);
            }
        }
        __syncthreads();

        // ---- LSTM pointwise: 512 (b,u) pairs / 256 threads ----
#pragma unroll
        for (int r = 0; r < 2; r++) {
            int pair = tid * 2 + r;
            int bb = pair >> 4;
            int u  = pair & 15;
            float pi = sg[bb * 68 + u]      + bias[u];
            float pf = sg[bb * 68 + 16 + u] + bias[16 + u];
            float pg = sg[bb * 68 + 32 + u] + bias[32 + u];
            float po = sg[bb * 68 + 48 + u] + bias[48 + u];
            float ig = fsigmoid(pi);
            float fg = fsigmoid(pf);
            float gg = ftanh(pg);
            float og = fsigmoid(po);
            float cv = fg * cs[bb * 16 + u] + ig * gg;
            cs[bb * 16 + u] = cv;
            float hv = og * ftanh(cv);
            __stcg(&hw[(mbase + bb) * HH + jbase + u], hv);
            if (ARCHIVE)
                __stcg(&g_h1[(size_t)((mbase + bb) * TT + t) * HH + jbase + u], hv);
        }

        // prefetch x-part for t+1 (after red reads: protected by sync above)
        if (t + 1 < TT)
            stage_A<KIN>(as, HH / 32, K / 32, t + 1, mbase, nullptr, xin);

        publish(grp, jj, base + 2 + t);
    }
}

// ---------------- full model -----------------------------------------------
__global__ void __launch_bounds__(NTHR, 1)
lstm_persistent_kernel(const float* __restrict__ x,
                       const float* __restrict__ Wih0, const float* __restrict__ Whh0,
                       const float* __restrict__ bih0, const float* __restrict__ bhh0,
                       const float* __restrict__ Wih1, const float* __restrict__ Whh1,
                       const float* __restrict__ bih1, const float* __restrict__ bhh1,
                       const float* __restrict__ Wfc,  const float* __restrict__ bfc,
                       float* __restrict__ out) {
    const int grp = blockIdx.x >> 4;
    const int jj  = blockIdx.x & 15;

    if (threadIdx.x == 0)
        *(volatile int*)&g_flag[grp * 32 + jj] = 0;
    group_barrier_atomic(grp);

    run_layer<II, true >(0,      x,    Wih0, Whh0, bih0, bhh0);  // epochs 1..513
    run_layer<HH, false>(TT + 1, g_h1, Wih1, Whh1, bih1, bhh1);  // 514..1026

    if (jj == 0) {
        wait_group(grp, 2 * TT + 2);
        int mbase = grp * 32;
        for (int bb = threadIdx.x; bb < 32; bb += NTHR) {
            float s = bfc[0];
#pragma unroll 8
            for (int j = 0; j < HH; j++)
                s += __ldcg(&g_hbuf[0][(mbase + bb) * HH + j]) * Wfc[j];
            out[mbase + bb] = s;
        }
    }
}

// ---------------- harness entry --------------------------------------------
extern "C" void kernel_launch(void* const* d_in, const int* in_sizes, int n_in,
                              void* d_out, int out_size) {
    (void)in_sizes; (void)n_in; (void)out_size;
    const float* x    = (const float*)d_in[0];
    const float* Wih0 = (const float*)d_in[1];
    const float* Whh0 = (const float*)d_in[2];
    const float* bih0 = (const float*)d_in[3];
    const float* bhh0 = (const float*)d_in[4];
    const float* Wih1 = (const float*)d_in[5];
    const float* Whh1 = (const float*)d_in[6];
    const float* bih1 = (const float*)d_in[7];
    const float* bhh1 = (const float*)d_in[8];
    const float* Wfc  = (const float*)d_in[9];
    const float* bfc  = (const float*)d_in[10];

    // L1 footprint: 512*68 + 512*36 + 320 + 32*68 + 512 + 64 = 56320 floats
    const int smem_bytes = 56320 * 4;          // 225,280 B
    cudaFuncSetAttribute(lstm_persistent_kernel,
                         cudaFuncAttributeMaxDynamicSharedMemorySize, smem_bytes);

    lstm_persistent_kernel<<<GRID, NTHR, smem_bytes>>>(
        x, Wih0, Whh0, bih0, bhh0,
        Wih1, Whh1, bih1, bhh1,
        Wfc, bfc, (float*)d_out);
}